// round 1
// baseline (speedup 1.0000x reference)
#include <cuda_runtime.h>
#include <math.h>

#define B_SZ   4096
#define C_DIM  1024
#define N_DIM  256
#define M_DIM  64
#define G_COLS 198

// scratch for pre-activations of all 7 regressors, [B, 198]
__device__ float g_G[B_SZ * G_COLS];

__device__ __forceinline__ float softplus_f(float x) {
    return (x > 20.f) ? x : log1pf(expf(x));
}
__device__ __forceinline__ float sigmoid_f(float x) {
    return 1.f / (1.f + expf(-x));
}

// column c of the concatenated weight matrix [198, 1024]
__device__ __forceinline__ const float* wrow_ptr(
    int c, const float* Wk, const float* Wb, const float* Wg,
    const float* Ws, const float* Wgm, const float* We, const float* Wa)
{
    if (c < 64)   return Wk + (size_t)c * C_DIM;
    if (c == 64)  return Wb;
    if (c == 65)  return Wg;
    if (c < 69)   return Ws + (size_t)(c - 66) * C_DIM;
    if (c == 69)  return Wgm;
    if (c < 134)  return We + (size_t)(c - 70) * C_DIM;
    if (c < 198)  return Wa + (size_t)(c - 134) * C_DIM;
    return nullptr;
}
__device__ __forceinline__ float bias_val(
    int c, const float* bk, const float* bb, const float* bg,
    const float* bs, const float* bgm, const float* be, const float* ba)
{
    if (c < 64)   return bk[c];
    if (c == 64)  return bb[0];
    if (c == 65)  return bg[0];
    if (c < 69)   return bs[c - 66];
    if (c == 69)  return bgm[0];
    if (c < 134)  return be[c - 70];
    return ba[c - 134];
}

// ---------------------------------------------------------------------------
// Kernel 1: G[B,198] = emb @ Wcat.T + bcat
// 64x64 CTA tile, K-chunk 32, 16x16 threads, 4x4 micro-tile.
// ---------------------------------------------------------------------------
__global__ __launch_bounds__(256) void gates_gemm_kernel(
    const float* __restrict__ emb,
    const float* __restrict__ Wk,  const float* __restrict__ bk,
    const float* __restrict__ Wb,  const float* __restrict__ bb,
    const float* __restrict__ Wg,  const float* __restrict__ bg,
    const float* __restrict__ Ws,  const float* __restrict__ bs,
    const float* __restrict__ Wgm, const float* __restrict__ bgm,
    const float* __restrict__ We,  const float* __restrict__ be,
    const float* __restrict__ Wa,  const float* __restrict__ ba)
{
    __shared__ __align__(16) float As[32][68];   // [k][row]
    __shared__ __align__(16) float Bs[32][68];   // [k][col]

    const int tid = threadIdx.x;
    const int rowBase = blockIdx.x * 64;
    const int colBase = blockIdx.y * 64;

    const int lr = tid >> 3;   // 0..31
    const int kq = tid & 7;    // 0..7 (float4 slot within 32-k chunk)

    const float* wp0 = wrow_ptr(colBase + lr,      Wk, Wb, Wg, Ws, Wgm, We, Wa);
    const float* wp1 = wrow_ptr(colBase + lr + 32, Wk, Wb, Wg, Ws, Wgm, We, Wa);
    const float* arow0 = emb + (size_t)(rowBase + lr)      * C_DIM;
    const float* arow1 = emb + (size_t)(rowBase + lr + 32) * C_DIM;

    const int ty = tid >> 4;   // 0..15 (row micro-tile)
    const int tx = tid & 15;   // 0..15 (col micro-tile)

    float acc[4][4];
#pragma unroll
    for (int i = 0; i < 4; i++)
#pragma unroll
        for (int j = 0; j < 4; j++) acc[i][j] = 0.f;

    for (int k0 = 0; k0 < C_DIM; k0 += 32) {
        float4 a0 = *(const float4*)(arow0 + k0 + kq * 4);
        float4 a1 = *(const float4*)(arow1 + k0 + kq * 4);
        float4 b0 = wp0 ? *(const float4*)(wp0 + k0 + kq * 4) : make_float4(0.f, 0.f, 0.f, 0.f);
        float4 b1 = wp1 ? *(const float4*)(wp1 + k0 + kq * 4) : make_float4(0.f, 0.f, 0.f, 0.f);
        __syncthreads();   // previous chunk's compute done
        As[kq * 4 + 0][lr] = a0.x;  As[kq * 4 + 1][lr] = a0.y;
        As[kq * 4 + 2][lr] = a0.z;  As[kq * 4 + 3][lr] = a0.w;
        As[kq * 4 + 0][lr + 32] = a1.x;  As[kq * 4 + 1][lr + 32] = a1.y;
        As[kq * 4 + 2][lr + 32] = a1.z;  As[kq * 4 + 3][lr + 32] = a1.w;
        Bs[kq * 4 + 0][lr] = b0.x;  Bs[kq * 4 + 1][lr] = b0.y;
        Bs[kq * 4 + 2][lr] = b0.z;  Bs[kq * 4 + 3][lr] = b0.w;
        Bs[kq * 4 + 0][lr + 32] = b1.x;  Bs[kq * 4 + 1][lr + 32] = b1.y;
        Bs[kq * 4 + 2][lr + 32] = b1.z;  Bs[kq * 4 + 3][lr + 32] = b1.w;
        __syncthreads();
#pragma unroll
        for (int k = 0; k < 32; k++) {
            float4 av = *(const float4*)&As[k][ty * 4];
            float4 bv = *(const float4*)&Bs[k][tx * 4];
            float ar[4] = {av.x, av.y, av.z, av.w};
            float br[4] = {bv.x, bv.y, bv.z, bv.w};
#pragma unroll
            for (int i = 0; i < 4; i++)
#pragma unroll
                for (int j = 0; j < 4; j++) acc[i][j] += ar[i] * br[j];
        }
    }

#pragma unroll
    for (int i = 0; i < 4; i++) {
        int r = rowBase + ty * 4 + i;
        float* gout = g_G + (size_t)r * G_COLS;
#pragma unroll
        for (int j = 0; j < 4; j++) {
            int c = colBase + tx * 4 + j;
            if (c < G_COLS)
                gout[c] = acc[i][j] + bias_val(c, bk, bb, bg, bs, bgm, be, ba);
        }
    }
}

// ---------------------------------------------------------------------------
// Kernel 2: fused NTM write head. One CTA per batch row.
// memory row (64KB) cached in SMEM (padded stride 65) -> one HBM read.
// ---------------------------------------------------------------------------
__device__ __forceinline__ float blockReduceSum256(float v, volatile float* sRed) {
#pragma unroll
    for (int o = 16; o > 0; o >>= 1) v += __shfl_xor_sync(0xffffffffu, v, o);
    __syncthreads();                       // protect previous sRed contents
    if ((threadIdx.x & 31) == 0) sRed[threadIdx.x >> 5] = v;
    __syncthreads();
    return sRed[0] + sRed[1] + sRed[2] + sRed[3]
         + sRed[4] + sRed[5] + sRed[6] + sRed[7];
}
__device__ __forceinline__ float blockReduceMax256(float v, volatile float* sRed) {
#pragma unroll
    for (int o = 16; o > 0; o >>= 1) v = fmaxf(v, __shfl_xor_sync(0xffffffffu, v, o));
    __syncthreads();
    if ((threadIdx.x & 31) == 0) sRed[threadIdx.x >> 5] = v;
    __syncthreads();
    float t = fmaxf(fmaxf(fmaxf(sRed[0], sRed[1]), fmaxf(sRed[2], sRed[3])),
                    fmaxf(fmaxf(sRed[4], sRed[5]), fmaxf(sRed[6], sRed[7])));
    return t;
}

__global__ __launch_bounds__(256) void write_head_kernel(
    const float* __restrict__ w_prev,
    const float* __restrict__ memory,
    float* __restrict__ out_w,
    float* __restrict__ out_mem)
{
    extern __shared__ float sMem[];        // [256 * 65] padded memory tile
    __shared__ float sK[64], sE[64], sA[64];
    __shared__ float sWg[256];
    __shared__ float sW[256];
    __shared__ float sRed[8];
    __shared__ float sScal[8];             // beta,g,s0,s1,s2,gamma

    const int b = blockIdx.x;
    const int tid = threadIdx.x;
    const float* Grow = g_G + (size_t)b * G_COLS;

    float kv = 0.f;
    if (tid < 64) {
        kv = Grow[tid];
        sK[tid] = kv;
        sE[tid] = sigmoid_f(Grow[70 + tid]);
        sA[tid] = Grow[134 + tid];
    } else if (tid == 64) {
        sScal[0] = softplus_f(Grow[64]);            // beta
    } else if (tid == 65) {
        sScal[1] = sigmoid_f(Grow[65]);             // g
    } else if (tid == 66) {
        sScal[5] = 1.f + softplus_f(Grow[69]);      // gamma
    } else if (tid == 67) {
        float x0 = Grow[66], x1 = Grow[67], x2 = Grow[68];
        float mx = fmaxf(x0, fmaxf(x1, x2));
        float e0 = expf(x0 - mx), e1 = expf(x1 - mx), e2 = expf(x2 - mx);
        float inv = 1.f / (e0 + e1 + e2);
        sScal[2] = e0 * inv; sScal[3] = e1 * inv; sScal[4] = e2 * inv;
    }
    // ||k||^2 partial (warps 0,1 fully active for tid<64)
    if (tid < 64) {
        float kk = kv * kv;
#pragma unroll
        for (int o = 16; o > 0; o >>= 1) kk += __shfl_xor_sync(0xffffffffu, kk, o);
        if ((tid & 31) == 0) sRed[tid >> 5] = kk;
    }

    // stage memory row into SMEM (coalesced float4 -> padded scalar stores)
    const float4* memv = (const float4*)(memory + (size_t)b * (N_DIM * M_DIM));
#pragma unroll 4
    for (int i4 = tid; i4 < (N_DIM * M_DIM / 4); i4 += 256) {
        float4 v = memv[i4];
        int n = i4 >> 4;
        int m0 = (i4 & 15) << 2;
        float* p = sMem + n * 65 + m0;
        p[0] = v.x; p[1] = v.y; p[2] = v.z; p[3] = v.w;
    }
    __syncthreads();

    const float knorm = sqrtf(sRed[0] + sRed[1]);
    const float beta  = sScal[0];
    const float g     = sScal[1];
    const float s0    = sScal[2], s1 = sScal[3], s2 = sScal[4];
    const float gamma = sScal[5];

    // content addressing: thread per slot n
    const int n = tid;
    const float* rowp = sMem + n * 65;
    float dot = 0.f, nsq = 0.f;
#pragma unroll
    for (int m = 0; m < 64; m++) {
        float v = rowp[m];
        dot += v * sK[m];
        nsq += v * v;
    }
    float cosv = dot / (fmaxf(sqrtf(nsq), 1e-8f) * fmaxf(knorm, 1e-8f));
    float logit = beta * cosv;

    float mx  = blockReduceMax256(logit, sRed);
    float ex  = expf(logit - mx);
    float sum = blockReduceSum256(ex, sRed);
    float wc  = ex / sum;

    float wg = g * wc + (1.f - g) * w_prev[(size_t)b * N_DIM + n];
    sWg[n] = wg;
    __syncthreads();

    float wsh = s0 * sWg[(n + 255) & 255] + s1 * wg + s2 * sWg[(n + 1) & 255];
    float wpow = powf(wsh, gamma);
    float psum = blockReduceSum256(wpow, sRed);
    float wfin = wpow / (psum + 1e-16f);
    out_w[(size_t)b * N_DIM + n] = wfin;
    sW[n] = wfin;
    __syncthreads();

    // erase/add update, streamed back out
    float4* outv = (float4*)(out_mem + (size_t)b * (N_DIM * M_DIM));
#pragma unroll 4
    for (int i4 = tid; i4 < (N_DIM * M_DIM / 4); i4 += 256) {
        int nn = i4 >> 4;
        int m0 = (i4 & 15) << 2;
        float wn = sW[nn];
        const float* p = sMem + nn * 65 + m0;
        float4 r;
        r.x = p[0] * (1.f - wn * sE[m0 + 0]) + wn * sA[m0 + 0];
        r.y = p[1] * (1.f - wn * sE[m0 + 1]) + wn * sA[m0 + 1];
        r.z = p[2] * (1.f - wn * sE[m0 + 2]) + wn * sA[m0 + 2];
        r.w = p[3] * (1.f - wn * sE[m0 + 3]) + wn * sA[m0 + 3];
        outv[i4] = r;
    }
}

// ---------------------------------------------------------------------------
extern "C" void kernel_launch(void* const* d_in, const int* in_sizes, int n_in,
                              void* d_out, int out_size)
{
    const float* emb    = (const float*)d_in[0];
    const float* w_prev = (const float*)d_in[1];
    const float* memory = (const float*)d_in[2];
    const float* Wk  = (const float*)d_in[3];  const float* bk  = (const float*)d_in[4];
    const float* Wb  = (const float*)d_in[5];  const float* bb  = (const float*)d_in[6];
    const float* Wg  = (const float*)d_in[7];  const float* bg  = (const float*)d_in[8];
    const float* Ws  = (const float*)d_in[9];  const float* bs  = (const float*)d_in[10];
    const float* Wgm = (const float*)d_in[11]; const float* bgm = (const float*)d_in[12];
    const float* We  = (const float*)d_in[13]; const float* be  = (const float*)d_in[14];
    const float* Wa  = (const float*)d_in[15]; const float* ba  = (const float*)d_in[16];

    float* out_w   = (float*)d_out;                       // [B, N]
    float* out_mem = out_w + (size_t)B_SZ * N_DIM;        // [B, N, M]

    const int smem_bytes = N_DIM * 65 * sizeof(float);    // 66,560 B
    cudaFuncSetAttribute(write_head_kernel,
                         cudaFuncAttributeMaxDynamicSharedMemorySize, smem_bytes);

    dim3 g1(B_SZ / 64, 4, 1);
    gates_gemm_kernel<<<g1, 256>>>(emb, Wk, bk, Wb, bb, Wg, bg, Ws, bs,
                                   Wgm, bgm, We, be, Wa, ba);
    write_head_kernel<<<B_SZ, 256, smem_bytes>>>(w_prev, memory, out_w, out_mem);
}

// round 5
// speedup vs baseline: 1.2611x; 1.2611x over previous
#include <cuda_runtime.h>
#include <cuda_bf16.h>
#include <math.h>
#include <stdint.h>

#define B_SZ   4096
#define C_DIM  1024
#define N_DIM  256
#define M_DIM  64
#define G_COLS 198

// ---------------------------------------------------------------------------
// device scratch
// ---------------------------------------------------------------------------
__device__ float g_G[B_SZ * G_COLS];                 // gate pre-activations
__device__ __nv_bfloat16 g_Bhi[256 * C_DIM];         // W concat, bf16 hi
__device__ __nv_bfloat16 g_Blo[256 * C_DIM];         // W concat, bf16 lo
__device__ float g_bias[256];

__device__ __forceinline__ float softplus_f(float x) {
    return (x > 20.f) ? x : log1pf(expf(x));
}
__device__ __forceinline__ float sigmoid_f(float x) {
    return 1.f / (1.f + expf(-x));
}
__device__ __forceinline__ uint32_t bf2u(__nv_bfloat162 v) {
    return *reinterpret_cast<uint32_t*>(&v);
}

// column c of the concatenated weight matrix [198, 1024]
__device__ __forceinline__ const float* wrow_ptr(
    int c, const float* Wk, const float* Wb, const float* Wg,
    const float* Ws, const float* Wgm, const float* We, const float* Wa)
{
    if (c < 64)   return Wk + (size_t)c * C_DIM;
    if (c == 64)  return Wb;
    if (c == 65)  return Wg;
    if (c < 69)   return Ws + (size_t)(c - 66) * C_DIM;
    if (c == 69)  return Wgm;
    if (c < 134)  return We + (size_t)(c - 70) * C_DIM;
    if (c < 198)  return Wa + (size_t)(c - 134) * C_DIM;
    return nullptr;
}
__device__ __forceinline__ float bias_val(
    int c, const float* bk, const float* bb, const float* bg,
    const float* bs, const float* bgm, const float* be, const float* ba)
{
    if (c < 64)   return bk[c];
    if (c == 64)  return bb[0];
    if (c == 65)  return bg[0];
    if (c < 69)   return bs[c - 66];
    if (c == 69)  return bgm[0];
    if (c < 134)  return be[c - 70];
    return ba[c - 134];
}

// ---------------------------------------------------------------------------
// Kernel 0: convert concatenated W to bf16 hi/lo + bias vector
// ---------------------------------------------------------------------------
__global__ __launch_bounds__(256) void conv_w_kernel(
    const float* __restrict__ Wk,  const float* __restrict__ bk,
    const float* __restrict__ Wb,  const float* __restrict__ bb,
    const float* __restrict__ Wg,  const float* __restrict__ bg,
    const float* __restrict__ Ws,  const float* __restrict__ bs,
    const float* __restrict__ Wgm, const float* __restrict__ bgm,
    const float* __restrict__ We,  const float* __restrict__ be,
    const float* __restrict__ Wa,  const float* __restrict__ ba)
{
    const int row = blockIdx.x;             // 0..255 (N dim of GEMM)
    const int tid = threadIdx.x;
    const float* src = wrow_ptr(row, Wk, Wb, Wg, Ws, Wgm, We, Wa);
    for (int k = tid; k < C_DIM; k += 256) {
        float x = src ? src[k] : 0.f;
        __nv_bfloat16 hi = __float2bfloat16_rn(x);
        __nv_bfloat16 lo = __float2bfloat16_rn(x - __bfloat162float(hi));
        g_Bhi[(size_t)row * C_DIM + k] = hi;
        g_Blo[(size_t)row * C_DIM + k] = lo;
    }
    if (tid == 0)
        g_bias[row] = (row < G_COLS) ? bias_val(row, bk, bb, bg, bs, bgm, be, ba) : 0.f;
}

// ---------------------------------------------------------------------------
// Kernel 1: HMMA bf16-split GEMM  G[4096,198] = emb @ Wcat.T + b
// mma.sync m16n8k16 (plain sm_80+ PTX, no tcgen05).
// CTA tile 128x128, 8 warps (2m x 4n), warp tile 64x32.
// K-chunk = 32 fp32; per chunk: {Ahi*Bhi + Ahi*Blo + Alo*Bhi}.
// Register-prefetch pipeline: G2R(c+1) issued before compute(c).
// ---------------------------------------------------------------------------
#define KC 32
#define NC (C_DIM / KC)          // 32 chunks
#define KPAD 40                  // bf16 elems per smem row (80 bytes)

__device__ __forceinline__ void mma_bf16(float* c, const uint32_t* a, const uint32_t* b) {
    asm volatile(
        "mma.sync.aligned.m16n8k16.row.col.f32.bf16.bf16.f32 "
        "{%0,%1,%2,%3}, {%4,%5,%6,%7}, {%8,%9}, {%0,%1,%2,%3};"
        : "+f"(c[0]), "+f"(c[1]), "+f"(c[2]), "+f"(c[3])
        : "r"(a[0]), "r"(a[1]), "r"(a[2]), "r"(a[3]), "r"(b[0]), "r"(b[1]));
}

__global__ __launch_bounds__(256) void gates_gemm_mma(const float* __restrict__ emb)
{
    __shared__ __align__(16) char sAh[128 * KPAD * 2];
    __shared__ __align__(16) char sAl[128 * KPAD * 2];
    __shared__ __align__(16) char sBh[128 * KPAD * 2];
    __shared__ __align__(16) char sBl[128 * KPAD * 2];

    const int tid  = threadIdx.x;
    const int wid  = tid >> 5;
    const int lane = tid & 31;
    const int wm   = wid & 1;       // 0..1  (m: 64 rows each)
    const int wn   = wid >> 1;      // 0..3  (n: 32 cols each)
    const int rowBase = blockIdx.x * 128;
    const int colBase = blockIdx.y * 128;

    float acc[4][4][4];
#pragma unroll
    for (int mt = 0; mt < 4; ++mt)
#pragma unroll
        for (int nt = 0; nt < 4; ++nt)
#pragma unroll
            for (int i = 0; i < 4; ++i) acc[mt][nt][i] = 0.f;

    float4 apf[4];
    uint4  bpf[4];

    auto g2r = [&](int c) {
        const int k0 = c * KC;
#pragma unroll
        for (int t = 0; t < 4; ++t) {
            const int i4  = t * 256 + tid;       // 0..1023
            const int row = i4 >> 3;
            const int kq  = i4 & 7;
            apf[t] = *reinterpret_cast<const float4*>(
                emb + (size_t)(rowBase + row) * C_DIM + k0 + kq * 4);
        }
#pragma unroll
        for (int t = 0; t < 4; ++t) {
            const int i   = t * 256 + tid;       // 0..1023
            const int til = i >> 9;              // 0 = hi, 1 = lo
            const int j   = i & 511;
            const int row = j >> 2;
            const int q   = j & 3;
            const __nv_bfloat16* src = (til == 0) ? g_Bhi : g_Blo;
            bpf[t] = *reinterpret_cast<const uint4*>(
                src + (size_t)(colBase + row) * C_DIM + k0 + q * 8);
        }
    };
    auto r2s = [&]() {
#pragma unroll
        for (int t = 0; t < 4; ++t) {
            const int i4  = t * 256 + tid;
            const int row = i4 >> 3;
            const int kq  = i4 & 7;
            const float4 v = apf[t];
            __nv_bfloat162 h01 = __floats2bfloat162_rn(v.x, v.y);
            __nv_bfloat162 h23 = __floats2bfloat162_rn(v.z, v.w);
            const float lx = v.x - __bfloat162float(h01.x);
            const float ly = v.y - __bfloat162float(h01.y);
            const float lz = v.z - __bfloat162float(h23.x);
            const float lw = v.w - __bfloat162float(h23.y);
            __nv_bfloat162 l01 = __floats2bfloat162_rn(lx, ly);
            __nv_bfloat162 l23 = __floats2bfloat162_rn(lz, lw);
            *reinterpret_cast<uint2*>(sAh + row * (KPAD * 2) + kq * 8) =
                make_uint2(bf2u(h01), bf2u(h23));
            *reinterpret_cast<uint2*>(sAl + row * (KPAD * 2) + kq * 8) =
                make_uint2(bf2u(l01), bf2u(l23));
        }
#pragma unroll
        for (int t = 0; t < 4; ++t) {
            const int i   = t * 256 + tid;
            const int til = i >> 9;
            const int j   = i & 511;
            const int row = j >> 2;
            const int q   = j & 3;
            char* dst = (til == 0) ? sBh : sBl;
            *reinterpret_cast<uint4*>(dst + row * (KPAD * 2) + q * 16) = bpf[t];
        }
    };

    g2r(0);
    r2s();
    __syncthreads();

    const int ar = lane >> 2;          // 0..7
    const int ac = (lane & 3) * 2;     // 0,2,4,6

    for (int c = 0; c < NC; ++c) {
        if (c + 1 < NC) g2r(c + 1);    // gmem loads in flight during compute

#pragma unroll
        for (int kk = 0; kk < KC; kk += 16) {
            uint32_t ah[4][4], al[4][4], bh[4][2], bl[4][2];
#pragma unroll
            for (int mt = 0; mt < 4; ++mt) {
                const int r0 = (wm * 64 + mt * 16 + ar) * (KPAD * 2);
                const int r8 = r0 + 8 * (KPAD * 2);
                const int c0 = (kk + ac) * 2;
                ah[mt][0] = *reinterpret_cast<const uint32_t*>(sAh + r0 + c0);
                ah[mt][1] = *reinterpret_cast<const uint32_t*>(sAh + r8 + c0);
                ah[mt][2] = *reinterpret_cast<const uint32_t*>(sAh + r0 + c0 + 16);
                ah[mt][3] = *reinterpret_cast<const uint32_t*>(sAh + r8 + c0 + 16);
                al[mt][0] = *reinterpret_cast<const uint32_t*>(sAl + r0 + c0);
                al[mt][1] = *reinterpret_cast<const uint32_t*>(sAl + r8 + c0);
                al[mt][2] = *reinterpret_cast<const uint32_t*>(sAl + r0 + c0 + 16);
                al[mt][3] = *reinterpret_cast<const uint32_t*>(sAl + r8 + c0 + 16);
            }
#pragma unroll
            for (int nt = 0; nt < 4; ++nt) {
                const int rn = (wn * 32 + nt * 8 + ar) * (KPAD * 2);
                const int c0 = (kk + ac) * 2;
                bh[nt][0] = *reinterpret_cast<const uint32_t*>(sBh + rn + c0);
                bh[nt][1] = *reinterpret_cast<const uint32_t*>(sBh + rn + c0 + 16);
                bl[nt][0] = *reinterpret_cast<const uint32_t*>(sBl + rn + c0);
                bl[nt][1] = *reinterpret_cast<const uint32_t*>(sBl + rn + c0 + 16);
            }
#pragma unroll
            for (int mt = 0; mt < 4; ++mt)
#pragma unroll
                for (int nt = 0; nt < 4; ++nt) {
                    mma_bf16(acc[mt][nt], ah[mt], bh[nt]);
                    mma_bf16(acc[mt][nt], ah[mt], bl[nt]);
                    mma_bf16(acc[mt][nt], al[mt], bh[nt]);
                }
        }

        if (c + 1 < NC) {
            __syncthreads();    // all warps done reading smem
            r2s();              // overwrite with next chunk
            __syncthreads();    // stores visible
        }
    }

    // epilogue: D[row][col] layout of m16n8 f32 fragment
#pragma unroll
    for (int mt = 0; mt < 4; ++mt) {
        const int row0 = rowBase + wm * 64 + mt * 16 + (lane >> 2);
        float* g0 = g_G + (size_t)row0 * G_COLS;
        float* g1 = g_G + (size_t)(row0 + 8) * G_COLS;
#pragma unroll
        for (int nt = 0; nt < 4; ++nt) {
            const int col = colBase + wn * 32 + nt * 8 + (lane & 3) * 2;
            if (col < G_COLS) {
                g0[col] = acc[mt][nt][0] + g_bias[col];
                g1[col] = acc[mt][nt][2] + g_bias[col];
            }
            if (col + 1 < G_COLS) {
                g0[col + 1] = acc[mt][nt][1] + g_bias[col + 1];
                g1[col + 1] = acc[mt][nt][3] + g_bias[col + 1];
            }
        }
    }
}

// ---------------------------------------------------------------------------
// Kernel 2: fused NTM write head. One CTA (512 thr) per batch row.
// memory row (64KB) cached in SMEM (padded stride 65) -> one HBM read.
// ---------------------------------------------------------------------------
__global__ __launch_bounds__(512) void write_head_kernel(
    const float* __restrict__ w_prev,
    const float* __restrict__ memory,
    float* __restrict__ out_w,
    float* __restrict__ out_mem)
{
    extern __shared__ float sMem[];        // [256 * 65] padded memory tile
    __shared__ float sK[64], sE[64], sA[64];
    __shared__ float sWg[256];
    __shared__ float sW[256];
    __shared__ float sRed[16];
    __shared__ float sKred[2];
    __shared__ float sScal[8];             // beta,g,s0,s1,s2,gamma

    const int b = blockIdx.x;
    const int tid = threadIdx.x;
    const int widx = tid >> 5;
    const float* Grow = g_G + (size_t)b * G_COLS;

    if (tid < 64) {
        float kv = Grow[tid];
        sK[tid] = kv;
        sE[tid] = sigmoid_f(Grow[70 + tid]);
        sA[tid] = Grow[134 + tid];
        float kk = kv * kv;
#pragma unroll
        for (int o = 16; o > 0; o >>= 1) kk += __shfl_xor_sync(0xffffffffu, kk, o);
        if ((tid & 31) == 0) sKred[tid >> 5] = kk;
    } else if (tid == 64) {
        sScal[0] = softplus_f(Grow[64]);            // beta
    } else if (tid == 65) {
        sScal[1] = sigmoid_f(Grow[65]);             // g
    } else if (tid == 66) {
        sScal[5] = 1.f + softplus_f(Grow[69]);      // gamma
    } else if (tid == 67) {
        float x0 = Grow[66], x1 = Grow[67], x2 = Grow[68];
        float mx = fmaxf(x0, fmaxf(x1, x2));
        float e0 = expf(x0 - mx), e1 = expf(x1 - mx), e2 = expf(x2 - mx);
        float inv = 1.f / (e0 + e1 + e2);
        sScal[2] = e0 * inv; sScal[3] = e1 * inv; sScal[4] = e2 * inv;
    }

    // stage memory row into SMEM (streaming loads, evict-first)
    const float4* memv = (const float4*)(memory + (size_t)b * (N_DIM * M_DIM));
#pragma unroll
    for (int ii = 0; ii < (N_DIM * M_DIM / 4) / 512; ++ii) {
        const int i4 = ii * 512 + tid;
        float4 v = __ldcs(memv + i4);
        const int n = i4 >> 4;
        const int m0 = (i4 & 15) << 2;
        float* p = sMem + n * 65 + m0;
        p[0] = v.x; p[1] = v.y; p[2] = v.z; p[3] = v.w;
    }
    __syncthreads();

    const float knorm = sqrtf(sKred[0] + sKred[1]);
    const float beta  = sScal[0];
    const float g     = sScal[1];
    const float s0    = sScal[2], s1 = sScal[3], s2 = sScal[4];
    const float gamma = sScal[5];

    // content addressing: thread per slot n (tid < 256)
    const int n = tid;
    float logit = -INFINITY;
    if (tid < 256) {
        const float* rowp = sMem + n * 65;
        float dot = 0.f, nsq = 0.f;
#pragma unroll
        for (int m = 0; m < 64; m++) {
            float v = rowp[m];
            dot += v * sK[m];
            nsq += v * v;
        }
        float cosv = dot / (fmaxf(sqrtf(nsq), 1e-8f) * fmaxf(knorm, 1e-8f));
        logit = beta * cosv;
    }

    // block max over 512 threads
    float mv = logit;
#pragma unroll
    for (int o = 16; o > 0; o >>= 1) mv = fmaxf(mv, __shfl_xor_sync(0xffffffffu, mv, o));
    if ((tid & 31) == 0) sRed[widx] = mv;
    __syncthreads();
    float mx = sRed[0];
#pragma unroll
    for (int i = 1; i < 16; i++) mx = fmaxf(mx, sRed[i]);

    float ex = (tid < 256) ? expf(logit - mx) : 0.f;
    float sv = ex;
#pragma unroll
    for (int o = 16; o > 0; o >>= 1) sv += __shfl_xor_sync(0xffffffffu, sv, o);
    __syncthreads();                       // sRed consumed above
    if ((tid & 31) == 0) sRed[widx] = sv;
    __syncthreads();
    float sum = 0.f;
#pragma unroll
    for (int i = 0; i < 16; i++) sum += sRed[i];

    float wg = 0.f;
    if (tid < 256) {
        float wc = ex / sum;
        wg = g * wc + (1.f - g) * w_prev[(size_t)b * N_DIM + n];
        sWg[n] = wg;
    }
    __syncthreads();

    float wpow = 0.f;
    if (tid < 256) {
        float wsh = s0 * sWg[(n + 255) & 255] + s1 * wg + s2 * sWg[(n + 1) & 255];
        wpow = powf(wsh, gamma);
    }
    float pv = wpow;
#pragma unroll
    for (int o = 16; o > 0; o >>= 1) pv += __shfl_xor_sync(0xffffffffu, pv, o);
    __syncthreads();
    if ((tid & 31) == 0) sRed[widx] = pv;
    __syncthreads();
    float psum = 0.f;
#pragma unroll
    for (int i = 0; i < 16; i++) psum += sRed[i];

    if (tid < 256) {
        float wfin = wpow / (psum + 1e-16f);
        out_w[(size_t)b * N_DIM + n] = wfin;
        sW[n] = wfin;
    }
    __syncthreads();

    // erase/add update, streamed back out
    float4* outv = (float4*)(out_mem + (size_t)b * (N_DIM * M_DIM));
#pragma unroll
    for (int ii = 0; ii < (N_DIM * M_DIM / 4) / 512; ++ii) {
        const int i4 = ii * 512 + tid;
        const int nn = i4 >> 4;
        const int m0 = (i4 & 15) << 2;
        float wn = sW[nn];
        const float* p = sMem + nn * 65 + m0;
        float4 r;
        r.x = p[0] * (1.f - wn * sE[m0 + 0]) + wn * sA[m0 + 0];
        r.y = p[1] * (1.f - wn * sE[m0 + 1]) + wn * sA[m0 + 1];
        r.z = p[2] * (1.f - wn * sE[m0 + 2]) + wn * sA[m0 + 2];
        r.w = p[3] * (1.f - wn * sE[m0 + 3]) + wn * sA[m0 + 3];
        __stcs(outv + i4, r);
    }
}

// ---------------------------------------------------------------------------
extern "C" void kernel_launch(void* const* d_in, const int* in_sizes, int n_in,
                              void* d_out, int out_size)
{
    const float* emb    = (const float*)d_in[0];
    const float* w_prev = (const float*)d_in[1];
    const float* memory = (const float*)d_in[2];
    const float* Wk  = (const float*)d_in[3];  const float* bk  = (const float*)d_in[4];
    const float* Wb  = (const float*)d_in[5];  const float* bb  = (const float*)d_in[6];
    const float* Wg  = (const float*)d_in[7];  const float* bg  = (const float*)d_in[8];
    const float* Ws  = (const float*)d_in[9];  const float* bs  = (const float*)d_in[10];
    const float* Wgm = (const float*)d_in[11]; const float* bgm = (const float*)d_in[12];
    const float* We  = (const float*)d_in[13]; const float* be  = (const float*)d_in[14];
    const float* Wa  = (const float*)d_in[15]; const float* ba  = (const float*)d_in[16];

    float* out_w   = (float*)d_out;                       // [B, N]
    float* out_mem = out_w + (size_t)B_SZ * N_DIM;        // [B, N, M]

    cudaFuncSetAttribute(write_head_kernel,
                         cudaFuncAttributeMaxDynamicSharedMemorySize,
                         N_DIM * 65 * (int)sizeof(float));

    conv_w_kernel<<<256, 256>>>(Wk, bk, Wb, bb, Wg, bg, Ws, bs,
                                Wgm, bgm, We, be, Wa, ba);
    gates_gemm_mma<<<dim3(B_SZ / 128, 2), 256>>>(emb);
    write_head_kernel<<<B_SZ, 512, N_DIM * 65 * sizeof(float)>>>(
        w_prev, memory, out_w, out_mem);
}

// round 7
// speedup vs baseline: 1.3781x; 1.0928x over previous
#include <cuda_runtime.h>
#include <cuda_bf16.h>
#include <math.h>
#include <stdint.h>

#define B_SZ   4096
#define C_DIM  1024
#define N_DIM  256
#define M_DIM  64
#define G_COLS 198

// ---------------------------------------------------------------------------
// device scratch
// ---------------------------------------------------------------------------
__device__ float g_G[B_SZ * G_COLS];                 // gate pre-activations
__device__ __nv_bfloat16 g_Bhi[256 * C_DIM];         // W concat, bf16 hi
__device__ __nv_bfloat16 g_Blo[256 * C_DIM];         // W concat, bf16 lo
__device__ float g_bias[256];

__device__ __forceinline__ float softplus_f(float x) {
    return (x > 20.f) ? x : log1pf(expf(x));
}
__device__ __forceinline__ float sigmoid_f(float x) {
    return 1.f / (1.f + expf(-x));
}
__device__ __forceinline__ uint32_t bf2u(__nv_bfloat162 v) {
    return *reinterpret_cast<uint32_t*>(&v);
}

// column c of the concatenated weight matrix [198, 1024]
__device__ __forceinline__ const float* wrow_ptr(
    int c, const float* Wk, const float* Wb, const float* Wg,
    const float* Ws, const float* Wgm, const float* We, const float* Wa)
{
    if (c < 64)   return Wk + (size_t)c * C_DIM;
    if (c == 64)  return Wb;
    if (c == 65)  return Wg;
    if (c < 69)   return Ws + (size_t)(c - 66) * C_DIM;
    if (c == 69)  return Wgm;
    if (c < 134)  return We + (size_t)(c - 70) * C_DIM;
    if (c < 198)  return Wa + (size_t)(c - 134) * C_DIM;
    return nullptr;
}
__device__ __forceinline__ float bias_val(
    int c, const float* bk, const float* bb, const float* bg,
    const float* bs, const float* bgm, const float* be, const float* ba)
{
    if (c < 64)   return bk[c];
    if (c == 64)  return bb[0];
    if (c == 65)  return bg[0];
    if (c < 69)   return bs[c - 66];
    if (c == 69)  return bgm[0];
    if (c < 134)  return be[c - 70];
    return ba[c - 134];
}

// ---------------------------------------------------------------------------
// Kernel 0: convert concatenated W to bf16 hi/lo + bias (1 float4/thread)
// ---------------------------------------------------------------------------
__global__ __launch_bounds__(256) void conv_w_kernel(
    const float* __restrict__ Wk,  const float* __restrict__ bk,
    const float* __restrict__ Wb,  const float* __restrict__ bb,
    const float* __restrict__ Wg,  const float* __restrict__ bg,
    const float* __restrict__ Ws,  const float* __restrict__ bs,
    const float* __restrict__ Wgm, const float* __restrict__ bgm,
    const float* __restrict__ We,  const float* __restrict__ be,
    const float* __restrict__ Wa,  const float* __restrict__ ba)
{
    const int row = blockIdx.x;             // 0..255 (N dim of GEMM)
    const int tid = threadIdx.x;
    const float* src = wrow_ptr(row, Wk, Wb, Wg, Ws, Wgm, We, Wa);
    const int k = tid * 4;                  // 256 threads x 4 = 1024
    float4 v = src ? *reinterpret_cast<const float4*>(src + k)
                   : make_float4(0.f, 0.f, 0.f, 0.f);
    __nv_bfloat162 h01 = __floats2bfloat162_rn(v.x, v.y);
    __nv_bfloat162 h23 = __floats2bfloat162_rn(v.z, v.w);
    __nv_bfloat162 l01 = __floats2bfloat162_rn(v.x - __bfloat162float(h01.x),
                                               v.y - __bfloat162float(h01.y));
    __nv_bfloat162 l23 = __floats2bfloat162_rn(v.z - __bfloat162float(h23.x),
                                               v.w - __bfloat162float(h23.y));
    *reinterpret_cast<uint2*>(g_Bhi + (size_t)row * C_DIM + k) =
        make_uint2(bf2u(h01), bf2u(h23));
    *reinterpret_cast<uint2*>(g_Blo + (size_t)row * C_DIM + k) =
        make_uint2(bf2u(l01), bf2u(l23));
    if (tid == 0)
        g_bias[row] = (row < G_COLS) ? bias_val(row, bk, bb, bg, bs, bgm, be, ba) : 0.f;
}

// ---------------------------------------------------------------------------
// Kernel 1: HMMA bf16-split GEMM  G[4096,198] = emb @ Wcat.T + b
// CTA tile 64x128, 8 warps (2m x 4n), warp tile 32x32; grid (64,2)=128 CTAs.
// K-chunk 32 fp32: {Ahi*Bhi + Ahi*Blo + Alo*Bhi}.
// 2-stage SMEM double buffer, register-prefetch G2R, 1 sync per chunk.
// ---------------------------------------------------------------------------
#define KC 32
#define NC (C_DIM / KC)          // 32 chunks
#define KPAD 40                  // bf16 elems per smem row (80 bytes)
#define ROWB (KPAD * 2)          // 80 bytes
#define A_BYTES (64 * ROWB)      // 5120
#define B_BYTES (128 * ROWB)     // 10240
#define OFF_AH 0
#define OFF_AL (A_BYTES)
#define OFF_BH (2 * A_BYTES)
#define OFF_BL (2 * A_BYTES + B_BYTES)
#define STAGE_BYTES (2 * A_BYTES + 2 * B_BYTES)   // 30720
#define GEMM_SMEM (2 * STAGE_BYTES)               // 61440

__device__ __forceinline__ void mma_bf16(float* c, const uint32_t* a, const uint32_t* b) {
    asm volatile(
        "mma.sync.aligned.m16n8k16.row.col.f32.bf16.bf16.f32 "
        "{%0,%1,%2,%3}, {%4,%5,%6,%7}, {%8,%9}, {%0,%1,%2,%3};"
        : "+f"(c[0]), "+f"(c[1]), "+f"(c[2]), "+f"(c[3])
        : "r"(a[0]), "r"(a[1]), "r"(a[2]), "r"(a[3]), "r"(b[0]), "r"(b[1]));
}

__global__ __launch_bounds__(256) void gates_gemm_mma(const float* __restrict__ emb)
{
    extern __shared__ __align__(16) char smem[];

    const int tid  = threadIdx.x;
    const int wid  = tid >> 5;
    const int lane = tid & 31;
    const int wm   = wid & 1;       // 0..1  (m: 32 rows each)
    const int wn   = wid >> 1;      // 0..3  (n: 32 cols each)
    const int rowBase = blockIdx.x * 64;
    const int colBase = blockIdx.y * 128;

    float acc[2][4][4];
#pragma unroll
    for (int mt = 0; mt < 2; ++mt)
#pragma unroll
        for (int nt = 0; nt < 4; ++nt)
#pragma unroll
            for (int i = 0; i < 4; ++i) acc[mt][nt][i] = 0.f;

    float4 apf[2];
    uint4  bpf[4];

    auto g2r = [&](int c) {
        const int k0 = c * KC;
#pragma unroll
        for (int t = 0; t < 2; ++t) {        // A: 64 rows x 8 float4
            const int i4  = t * 256 + tid;   // 0..511
            const int row = i4 >> 3;
            const int kq  = i4 & 7;
            apf[t] = *reinterpret_cast<const float4*>(
                emb + (size_t)(rowBase + row) * C_DIM + k0 + kq * 4);
        }
#pragma unroll
        for (int t = 0; t < 4; ++t) {        // B: hi/lo 128 rows x 4 uint4
            const int i   = t * 256 + tid;   // 0..1023
            const int til = i >> 9;          // 0 = hi, 1 = lo
            const int j   = i & 511;
            const int row = j >> 2;
            const int q   = j & 3;
            const __nv_bfloat16* src = (til == 0) ? g_Bhi : g_Blo;
            bpf[t] = *reinterpret_cast<const uint4*>(
                src + (size_t)(colBase + row) * C_DIM + k0 + q * 8);
        }
    };
    auto r2s = [&](int s) {
        char* st = smem + s * STAGE_BYTES;
#pragma unroll
        for (int t = 0; t < 2; ++t) {
            const int i4  = t * 256 + tid;
            const int row = i4 >> 3;
            const int kq  = i4 & 7;
            const float4 v = apf[t];
            __nv_bfloat162 h01 = __floats2bfloat162_rn(v.x, v.y);
            __nv_bfloat162 h23 = __floats2bfloat162_rn(v.z, v.w);
            __nv_bfloat162 l01 = __floats2bfloat162_rn(v.x - __bfloat162float(h01.x),
                                                       v.y - __bfloat162float(h01.y));
            __nv_bfloat162 l23 = __floats2bfloat162_rn(v.z - __bfloat162float(h23.x),
                                                       v.w - __bfloat162float(h23.y));
            *reinterpret_cast<uint2*>(st + OFF_AH + row * ROWB + kq * 8) =
                make_uint2(bf2u(h01), bf2u(h23));
            *reinterpret_cast<uint2*>(st + OFF_AL + row * ROWB + kq * 8) =
                make_uint2(bf2u(l01), bf2u(l23));
        }
#pragma unroll
        for (int t = 0; t < 4; ++t) {
            const int i   = t * 256 + tid;
            const int til = i >> 9;
            const int j   = i & 511;
            const int row = j >> 2;
            const int q   = j & 3;
            *reinterpret_cast<uint4*>(st + (til == 0 ? OFF_BH : OFF_BL)
                                      + row * ROWB + q * 16) = bpf[t];
        }
    };

    g2r(0);
    r2s(0);
    __syncthreads();

    const int ar = lane >> 2;          // 0..7
    const int ac = (lane & 3) * 2;     // 0,2,4,6

    for (int c = 0; c < NC; ++c) {
        if (c + 1 < NC) g2r(c + 1);    // gmem loads in flight during compute

        char* st = smem + (c & 1) * STAGE_BYTES;
#pragma unroll
        for (int kk = 0; kk < KC; kk += 16) {
            uint32_t ah[2][4], al[2][4], bh[4][2], bl[4][2];
            const int c0 = (kk + ac) * 2;
#pragma unroll
            for (int mt = 0; mt < 2; ++mt) {
                const int r0 = (wm * 32 + mt * 16 + ar) * ROWB;
                const int r8 = r0 + 8 * ROWB;
                ah[mt][0] = *reinterpret_cast<const uint32_t*>(st + OFF_AH + r0 + c0);
                ah[mt][1] = *reinterpret_cast<const uint32_t*>(st + OFF_AH + r8 + c0);
                ah[mt][2] = *reinterpret_cast<const uint32_t*>(st + OFF_AH + r0 + c0 + 16);
                ah[mt][3] = *reinterpret_cast<const uint32_t*>(st + OFF_AH + r8 + c0 + 16);
                al[mt][0] = *reinterpret_cast<const uint32_t*>(st + OFF_AL + r0 + c0);
                al[mt][1] = *reinterpret_cast<const uint32_t*>(st + OFF_AL + r8 + c0);
                al[mt][2] = *reinterpret_cast<const uint32_t*>(st + OFF_AL + r0 + c0 + 16);
                al[mt][3] = *reinterpret_cast<const uint32_t*>(st + OFF_AL + r8 + c0 + 16);
            }
#pragma unroll
            for (int nt = 0; nt < 4; ++nt) {
                const int rn = (wn * 32 + nt * 8 + ar) * ROWB;
                bh[nt][0] = *reinterpret_cast<const uint32_t*>(st + OFF_BH + rn + c0);
                bh[nt][1] = *reinterpret_cast<const uint32_t*>(st + OFF_BH + rn + c0 + 16);
                bl[nt][0] = *reinterpret_cast<const uint32_t*>(st + OFF_BL + rn + c0);
                bl[nt][1] = *reinterpret_cast<const uint32_t*>(st + OFF_BL + rn + c0 + 16);
            }
#pragma unroll
            for (int mt = 0; mt < 2; ++mt)
#pragma unroll
                for (int nt = 0; nt < 4; ++nt) {
                    mma_bf16(acc[mt][nt], ah[mt], bh[nt]);
                    mma_bf16(acc[mt][nt], ah[mt], bl[nt]);
                    mma_bf16(acc[mt][nt], al[mt], bh[nt]);
                }
        }

        if (c + 1 < NC) {
            r2s((c + 1) & 1);          // write other stage (safe: read 2 iters ago)
            __syncthreads();           // visibility for compute(c+1)
        }
    }

    // epilogue: D[row][col] layout of m16n8 f32 fragment
#pragma unroll
    for (int mt = 0; mt < 2; ++mt) {
        const int row0 = rowBase + wm * 32 + mt * 16 + (lane >> 2);
        float* g0 = g_G + (size_t)row0 * G_COLS;
        float* g1 = g_G + (size_t)(row0 + 8) * G_COLS;
#pragma unroll
        for (int nt = 0; nt < 4; ++nt) {
            const int col = colBase + wn * 32 + nt * 8 + (lane & 3) * 2;
            if (col < G_COLS) {
                g0[col] = acc[mt][nt][0] + g_bias[col];
                g1[col] = acc[mt][nt][2] + g_bias[col];
            }
            if (col + 1 < G_COLS) {
                g0[col + 1] = acc[mt][nt][1] + g_bias[col + 1];
                g1[col + 1] = acc[mt][nt][3] + g_bias[col + 1];
            }
        }
    }
}

// ---------------------------------------------------------------------------
// Kernel 2: fused NTM write head. One CTA (512 thr) per batch row.
// memory row (64KB) cached in SMEM (padded stride 65) -> one HBM read.
// ---------------------------------------------------------------------------
__global__ __launch_bounds__(512) void write_head_kernel(
    const float* __restrict__ w_prev,
    const float* __restrict__ memory,
    float* __restrict__ out_w,
    float* __restrict__ out_mem)
{
    extern __shared__ float sMem[];        // [256 * 65] padded memory tile
    __shared__ float sK[64], sE[64], sA[64];
    __shared__ float sWg[256];
    __shared__ float sW[256];
    __shared__ float sRed[16];
    __shared__ float sKred[2];
    __shared__ float sScal[8];             // beta,g,s0..s2,gamma

    const int b = blockIdx.x;
    const int tid = threadIdx.x;
    const int widx = tid >> 5;
    const float* Grow = g_G + (size_t)b * G_COLS;

    if (tid < 64) {
        float kv = Grow[tid];
        sK[tid] = kv;
        sE[tid] = sigmoid_f(Grow[70 + tid]);
        sA[tid] = Grow[134 + tid];
        float kk = kv * kv;
#pragma unroll
        for (int o = 16; o > 0; o >>= 1) kk += __shfl_xor_sync(0xffffffffu, kk, o);
        if ((tid & 31) == 0) sKred[tid >> 5] = kk;
    } else if (tid == 64) {
        sScal[0] = softplus_f(Grow[64]);            // beta
    } else if (tid == 65) {
        sScal[1] = sigmoid_f(Grow[65]);             // g
    } else if (tid == 66) {
        sScal[5] = 1.f + softplus_f(Grow[69]);      // gamma
    } else if (tid == 67) {
        float x0 = Grow[66], x1 = Grow[67], x2 = Grow[68];
        float mx = fmaxf(x0, fmaxf(x1, x2));
        float e0 = expf(x0 - mx), e1 = expf(x1 - mx), e2 = expf(x2 - mx);
        float inv = 1.f / (e0 + e1 + e2);
        sScal[2] = e0 * inv; sScal[3] = e1 * inv; sScal[4] = e2 * inv;
    }

    // stage memory row into SMEM (streaming loads, evict-first)
    const float4* memv = (const float4*)(memory + (size_t)b * (N_DIM * M_DIM));
#pragma unroll
    for (int ii = 0; ii < (N_DIM * M_DIM / 4) / 512; ++ii) {
        const int i4 = ii * 512 + tid;
        float4 v = __ldcs(memv + i4);
        const int n = i4 >> 4;
        const int m0 = (i4 & 15) << 2;
        float* p = sMem + n * 65 + m0;
        p[0] = v.x; p[1] = v.y; p[2] = v.z; p[3] = v.w;
    }
    __syncthreads();

    const float knorm = sqrtf(sKred[0] + sKred[1]);
    const float beta  = sScal[0];
    const float g     = sScal[1];
    const float s0    = sScal[2], s1 = sScal[3], s2 = sScal[4];
    const float gamma = sScal[5];

    // content addressing: thread per slot n (tid < 256)
    const int n = tid;
    float logit = -INFINITY;
    if (tid < 256) {
        const float* rowp = sMem + n * 65;
        float dot = 0.f, nsq = 0.f;
#pragma unroll
        for (int m = 0; m < 64; m++) {
            float v = rowp[m];
            dot += v * sK[m];
            nsq += v * v;
        }
        float cosv = dot / (fmaxf(sqrtf(nsq), 1e-8f) * fmaxf(knorm, 1e-8f));
        logit = beta * cosv;
    }

    // block max over 512 threads
    float mv = logit;
#pragma unroll
    for (int o = 16; o > 0; o >>= 1) mv = fmaxf(mv, __shfl_xor_sync(0xffffffffu, mv, o));
    if ((tid & 31) == 0) sRed[widx] = mv;
    __syncthreads();
    float mx = sRed[0];
#pragma unroll
    for (int i = 1; i < 16; i++) mx = fmaxf(mx, sRed[i]);

    float ex = (tid < 256) ? expf(logit - mx) : 0.f;
    float sv = ex;
#pragma unroll
    for (int o = 16; o > 0; o >>= 1) sv += __shfl_xor_sync(0xffffffffu, sv, o);
    __syncthreads();                       // sRed consumed above
    if ((tid & 31) == 0) sRed[widx] = sv;
    __syncthreads();
    float sum = 0.f;
#pragma unroll
    for (int i = 0; i < 16; i++) sum += sRed[i];

    float wg = 0.f;
    if (tid < 256) {
        float wc = ex / sum;
        wg = g * wc + (1.f - g) * w_prev[(size_t)b * N_DIM + n];
        sWg[n] = wg;
    }
    __syncthreads();

    float wpow = 0.f;
    if (tid < 256) {
        float wsh = s0 * sWg[(n + 255) & 255] + s1 * wg + s2 * sWg[(n + 1) & 255];
        wpow = powf(wsh, gamma);
    }
    float pv = wpow;
#pragma unroll
    for (int o = 16; o > 0; o >>= 1) pv += __shfl_xor_sync(0xffffffffu, pv, o);
    __syncthreads();
    if ((tid & 31) == 0) sRed[widx] = pv;
    __syncthreads();
    float psum = 0.f;
#pragma unroll
    for (int i = 0; i < 16; i++) psum += sRed[i];

    if (tid < 256) {
        float wfin = wpow / (psum + 1e-16f);
        out_w[(size_t)b * N_DIM + n] = wfin;
        sW[n] = wfin;
    }
    __syncthreads();

    // erase/add update, streamed back out
    float4* outv = (float4*)(out_mem + (size_t)b * (N_DIM * M_DIM));
#pragma unroll
    for (int ii = 0; ii < (N_DIM * M_DIM / 4) / 512; ++ii) {
        const int i4 = ii * 512 + tid;
        const int nn = i4 >> 4;
        const int m0 = (i4 & 15) << 2;
        float wn = sW[nn];
        const float* p = sMem + nn * 65 + m0;
        float4 r;
        r.x = p[0] * (1.f - wn * sE[m0 + 0]) + wn * sA[m0 + 0];
        r.y = p[1] * (1.f - wn * sE[m0 + 1]) + wn * sA[m0 + 1];
        r.z = p[2] * (1.f - wn * sE[m0 + 2]) + wn * sA[m0 + 2];
        r.w = p[3] * (1.f - wn * sE[m0 + 3]) + wn * sA[m0 + 3];
        __stcs(outv + i4, r);
    }
}

// ---------------------------------------------------------------------------
extern "C" void kernel_launch(void* const* d_in, const int* in_sizes, int n_in,
                              void* d_out, int out_size)
{
    const float* emb    = (const float*)d_in[0];
    const float* w_prev = (const float*)d_in[1];
    const float* memory = (const float*)d_in[2];
    const float* Wk  = (const float*)d_in[3];  const float* bk  = (const float*)d_in[4];
    const float* Wb  = (const float*)d_in[5];  const float* bb  = (const float*)d_in[6];
    const float* Wg  = (const float*)d_in[7];  const float* bg  = (const float*)d_in[8];
    const float* Ws  = (const float*)d_in[9];  const float* bs  = (const float*)d_in[10];
    const float* Wgm = (const float*)d_in[11]; const float* bgm = (const float*)d_in[12];
    const float* We  = (const float*)d_in[13]; const float* be  = (const float*)d_in[14];
    const float* Wa  = (const float*)d_in[15]; const float* ba  = (const float*)d_in[16];

    float* out_w   = (float*)d_out;                       // [B, N]
    float* out_mem = out_w + (size_t)B_SZ * N_DIM;        // [B, N, M]

    cudaFuncSetAttribute(gates_gemm_mma,
                         cudaFuncAttributeMaxDynamicSharedMemorySize, GEMM_SMEM);
    cudaFuncSetAttribute(write_head_kernel,
                         cudaFuncAttributeMaxDynamicSharedMemorySize,
                         N_DIM * 65 * (int)sizeof(float));

    conv_w_kernel<<<256, 256>>>(Wk, bk, Wb, bb, Wg, bg, Ws, bs,
                                Wgm, bgm, We, be, Wa, ba);
    gates_gemm_mma<<<dim3(B_SZ / 64, 2), 256, GEMM_SMEM>>>(emb);
    write_head_kernel<<<B_SZ, 512, N_DIM * 65 * sizeof(float)>>>(
        w_prev, memory, out_w, out_mem);
}

// round 8
// speedup vs baseline: 1.3943x; 1.0118x over previous
#include <cuda_runtime.h>
#include <cuda_bf16.h>
#include <math.h>
#include <stdint.h>

#define B_SZ   4096
#define C_DIM  1024
#define N_DIM  256
#define M_DIM  64
#define G_COLS 198

// ---------------------------------------------------------------------------
// device scratch
// ---------------------------------------------------------------------------
__device__ float g_G[B_SZ * G_COLS];                 // gate pre-activations
__device__ __nv_bfloat16 g_Bhi[256 * C_DIM];         // W concat, bf16 hi
__device__ __nv_bfloat16 g_Blo[256 * C_DIM];         // W concat, bf16 lo
__device__ float g_bias[256];

__device__ __forceinline__ float softplus_f(float x) {
    return (x > 20.f) ? x : log1pf(expf(x));
}
__device__ __forceinline__ float sigmoid_f(float x) {
    return 1.f / (1.f + expf(-x));
}
__device__ __forceinline__ uint32_t bf2u(__nv_bfloat162 v) {
    return *reinterpret_cast<uint32_t*>(&v);
}

// column c of the concatenated weight matrix [198, 1024]
__device__ __forceinline__ const float* wrow_ptr(
    int c, const float* Wk, const float* Wb, const float* Wg,
    const float* Ws, const float* Wgm, const float* We, const float* Wa)
{
    if (c < 64)   return Wk + (size_t)c * C_DIM;
    if (c == 64)  return Wb;
    if (c == 65)  return Wg;
    if (c < 69)   return Ws + (size_t)(c - 66) * C_DIM;
    if (c == 69)  return Wgm;
    if (c < 134)  return We + (size_t)(c - 70) * C_DIM;
    if (c < 198)  return Wa + (size_t)(c - 134) * C_DIM;
    return nullptr;
}
__device__ __forceinline__ float bias_val(
    int c, const float* bk, const float* bb, const float* bg,
    const float* bs, const float* bgm, const float* be, const float* ba)
{
    if (c < 64)   return bk[c];
    if (c == 64)  return bb[0];
    if (c == 65)  return bg[0];
    if (c < 69)   return bs[c - 66];
    if (c == 69)  return bgm[0];
    if (c < 134)  return be[c - 70];
    return ba[c - 134];
}

// ---------------------------------------------------------------------------
// Kernel 0: convert concatenated W to bf16 hi/lo + bias (1 float4/thread)
// ---------------------------------------------------------------------------
__global__ __launch_bounds__(256) void conv_w_kernel(
    const float* __restrict__ Wk,  const float* __restrict__ bk,
    const float* __restrict__ Wb,  const float* __restrict__ bb,
    const float* __restrict__ Wg,  const float* __restrict__ bg,
    const float* __restrict__ Ws,  const float* __restrict__ bs,
    const float* __restrict__ Wgm, const float* __restrict__ bgm,
    const float* __restrict__ We,  const float* __restrict__ be,
    const float* __restrict__ Wa,  const float* __restrict__ ba)
{
    const int row = blockIdx.x;             // 0..255 (N dim of GEMM)
    const int tid = threadIdx.x;
    const float* src = wrow_ptr(row, Wk, Wb, Wg, Ws, Wgm, We, Wa);
    const int k = tid * 4;                  // 256 threads x 4 = 1024
    float4 v = src ? *reinterpret_cast<const float4*>(src + k)
                   : make_float4(0.f, 0.f, 0.f, 0.f);
    __nv_bfloat162 h01 = __floats2bfloat162_rn(v.x, v.y);
    __nv_bfloat162 h23 = __floats2bfloat162_rn(v.z, v.w);
    __nv_bfloat162 l01 = __floats2bfloat162_rn(v.x - __bfloat162float(h01.x),
                                               v.y - __bfloat162float(h01.y));
    __nv_bfloat162 l23 = __floats2bfloat162_rn(v.z - __bfloat162float(h23.x),
                                               v.w - __bfloat162float(h23.y));
    *reinterpret_cast<uint2*>(g_Bhi + (size_t)row * C_DIM + k) =
        make_uint2(bf2u(h01), bf2u(h23));
    *reinterpret_cast<uint2*>(g_Blo + (size_t)row * C_DIM + k) =
        make_uint2(bf2u(l01), bf2u(l23));
    if (tid == 0)
        g_bias[row] = (row < G_COLS) ? bias_val(row, bk, bb, bg, bs, bgm, be, ba) : 0.f;
}

// ---------------------------------------------------------------------------
// Kernel 1: HMMA bf16-split GEMM  G[4096,198] = emb @ Wcat.T + b
// CTA tile 64x128, 8 warps (2m x 4n), warp tile 32x32; grid (64,2)=128 CTAs.
// K-chunk 32 fp32: {Ahi*Bhi + Ahi*Blo + Alo*Bhi}.
// 2-stage SMEM double buffer, register-prefetch G2R, 1 sync per chunk.
// ---------------------------------------------------------------------------
#define KC 32
#define NC (C_DIM / KC)          // 32 chunks
#define KPAD 40                  // bf16 elems per smem row (80 bytes)
#define ROWB (KPAD * 2)          // 80 bytes
#define A_BYTES (64 * ROWB)      // 5120
#define B_BYTES (128 * ROWB)     // 10240
#define OFF_AH 0
#define OFF_AL (A_BYTES)
#define OFF_BH (2 * A_BYTES)
#define OFF_BL (2 * A_BYTES + B_BYTES)
#define STAGE_BYTES (2 * A_BYTES + 2 * B_BYTES)   // 30720
#define GEMM_SMEM (2 * STAGE_BYTES)               // 61440

__device__ __forceinline__ void mma_bf16(float* c, const uint32_t* a, const uint32_t* b) {
    asm volatile(
        "mma.sync.aligned.m16n8k16.row.col.f32.bf16.bf16.f32 "
        "{%0,%1,%2,%3}, {%4,%5,%6,%7}, {%8,%9}, {%0,%1,%2,%3};"
        : "+f"(c[0]), "+f"(c[1]), "+f"(c[2]), "+f"(c[3])
        : "r"(a[0]), "r"(a[1]), "r"(a[2]), "r"(a[3]), "r"(b[0]), "r"(b[1]));
}

__global__ __launch_bounds__(256) void gates_gemm_mma(const float* __restrict__ emb)
{
    extern __shared__ __align__(16) char smem[];

    const int tid  = threadIdx.x;
    const int wid  = tid >> 5;
    const int lane = tid & 31;
    const int wm   = wid & 1;       // 0..1  (m: 32 rows each)
    const int wn   = wid >> 1;      // 0..3  (n: 32 cols each)
    const int rowBase = blockIdx.x * 64;
    const int colBase = blockIdx.y * 128;

    float acc[2][4][4];
#pragma unroll
    for (int mt = 0; mt < 2; ++mt)
#pragma unroll
        for (int nt = 0; nt < 4; ++nt)
#pragma unroll
            for (int i = 0; i < 4; ++i) acc[mt][nt][i] = 0.f;

    float4 apf[2];
    uint4  bpf[4];

    auto g2r = [&](int c) {
        const int k0 = c * KC;
#pragma unroll
        for (int t = 0; t < 2; ++t) {        // A: 64 rows x 8 float4
            const int i4  = t * 256 + tid;   // 0..511
            const int row = i4 >> 3;
            const int kq  = i4 & 7;
            apf[t] = *reinterpret_cast<const float4*>(
                emb + (size_t)(rowBase + row) * C_DIM + k0 + kq * 4);
        }
#pragma unroll
        for (int t = 0; t < 4; ++t) {        // B: hi/lo 128 rows x 4 uint4
            const int i   = t * 256 + tid;   // 0..1023
            const int til = i >> 9;          // 0 = hi, 1 = lo
            const int j   = i & 511;
            const int row = j >> 2;
            const int q   = j & 3;
            const __nv_bfloat16* src = (til == 0) ? g_Bhi : g_Blo;
            bpf[t] = *reinterpret_cast<const uint4*>(
                src + (size_t)(colBase + row) * C_DIM + k0 + q * 8);
        }
    };
    auto r2s = [&](int s) {
        char* st = smem + s * STAGE_BYTES;
#pragma unroll
        for (int t = 0; t < 2; ++t) {
            const int i4  = t * 256 + tid;
            const int row = i4 >> 3;
            const int kq  = i4 & 7;
            const float4 v = apf[t];
            __nv_bfloat162 h01 = __floats2bfloat162_rn(v.x, v.y);
            __nv_bfloat162 h23 = __floats2bfloat162_rn(v.z, v.w);
            __nv_bfloat162 l01 = __floats2bfloat162_rn(v.x - __bfloat162float(h01.x),
                                                       v.y - __bfloat162float(h01.y));
            __nv_bfloat162 l23 = __floats2bfloat162_rn(v.z - __bfloat162float(h23.x),
                                                       v.w - __bfloat162float(h23.y));
            *reinterpret_cast<uint2*>(st + OFF_AH + row * ROWB + kq * 8) =
                make_uint2(bf2u(h01), bf2u(h23));
            *reinterpret_cast<uint2*>(st + OFF_AL + row * ROWB + kq * 8) =
                make_uint2(bf2u(l01), bf2u(l23));
        }
#pragma unroll
        for (int t = 0; t < 4; ++t) {
            const int i   = t * 256 + tid;
            const int til = i >> 9;
            const int j   = i & 511;
            const int row = j >> 2;
            const int q   = j & 3;
            *reinterpret_cast<uint4*>(st + (til == 0 ? OFF_BH : OFF_BL)
                                      + row * ROWB + q * 16) = bpf[t];
        }
    };

    g2r(0);
    r2s(0);
    __syncthreads();

    const int ar = lane >> 2;          // 0..7
    const int ac = (lane & 3) * 2;     // 0,2,4,6

    for (int c = 0; c < NC; ++c) {
        if (c + 1 < NC) g2r(c + 1);    // gmem loads in flight during compute

        char* st = smem + (c & 1) * STAGE_BYTES;
#pragma unroll
        for (int kk = 0; kk < KC; kk += 16) {
            uint32_t ah[2][4], al[2][4], bh[4][2], bl[4][2];
            const int c0 = (kk + ac) * 2;
#pragma unroll
            for (int mt = 0; mt < 2; ++mt) {
                const int r0 = (wm * 32 + mt * 16 + ar) * ROWB;
                const int r8 = r0 + 8 * ROWB;
                ah[mt][0] = *reinterpret_cast<const uint32_t*>(st + OFF_AH + r0 + c0);
                ah[mt][1] = *reinterpret_cast<const uint32_t*>(st + OFF_AH + r8 + c0);
                ah[mt][2] = *reinterpret_cast<const uint32_t*>(st + OFF_AH + r0 + c0 + 16);
                ah[mt][3] = *reinterpret_cast<const uint32_t*>(st + OFF_AH + r8 + c0 + 16);
                al[mt][0] = *reinterpret_cast<const uint32_t*>(st + OFF_AL + r0 + c0);
                al[mt][1] = *reinterpret_cast<const uint32_t*>(st + OFF_AL + r8 + c0);
                al[mt][2] = *reinterpret_cast<const uint32_t*>(st + OFF_AL + r0 + c0 + 16);
                al[mt][3] = *reinterpret_cast<const uint32_t*>(st + OFF_AL + r8 + c0 + 16);
            }
#pragma unroll
            for (int nt = 0; nt < 4; ++nt) {
                const int rn = (wn * 32 + nt * 8 + ar) * ROWB;
                bh[nt][0] = *reinterpret_cast<const uint32_t*>(st + OFF_BH + rn + c0);
                bh[nt][1] = *reinterpret_cast<const uint32_t*>(st + OFF_BH + rn + c0 + 16);
                bl[nt][0] = *reinterpret_cast<const uint32_t*>(st + OFF_BL + rn + c0);
                bl[nt][1] = *reinterpret_cast<const uint32_t*>(st + OFF_BL + rn + c0 + 16);
            }
#pragma unroll
            for (int mt = 0; mt < 2; ++mt)
#pragma unroll
                for (int nt = 0; nt < 4; ++nt) {
                    mma_bf16(acc[mt][nt], ah[mt], bh[nt]);
                    mma_bf16(acc[mt][nt], ah[mt], bl[nt]);
                    mma_bf16(acc[mt][nt], al[mt], bh[nt]);
                }
        }

        if (c + 1 < NC) {
            r2s((c + 1) & 1);          // write other stage (safe: read 2 iters ago)
            __syncthreads();           // visibility for compute(c+1)
        }
    }

    // epilogue: D[row][col] layout of m16n8 f32 fragment
#pragma unroll
    for (int mt = 0; mt < 2; ++mt) {
        const int row0 = rowBase + wm * 32 + mt * 16 + (lane >> 2);
        float* g0 = g_G + (size_t)row0 * G_COLS;
        float* g1 = g_G + (size_t)(row0 + 8) * G_COLS;
#pragma unroll
        for (int nt = 0; nt < 4; ++nt) {
            const int col = colBase + wn * 32 + nt * 8 + (lane & 3) * 2;
            if (col < G_COLS) {
                g0[col] = acc[mt][nt][0] + g_bias[col];
                g1[col] = acc[mt][nt][2] + g_bias[col];
            }
            if (col + 1 < G_COLS) {
                g0[col + 1] = acc[mt][nt][1] + g_bias[col + 1];
                g1[col + 1] = acc[mt][nt][3] + g_bias[col + 1];
            }
        }
    }
}

// ---------------------------------------------------------------------------
// Kernel 2: fused NTM write head. One CTA (512 thr) per batch row.
// Memory tile held in REGISTERS (8 float4/thread); no SMEM staging.
// Row n's 64 floats live in the 16 lanes of one half-warp:
//   i4 = ii*512 + tid  ->  n = ii*32 + (tid>>4),  m0 = (tid&15)*4
// Dot/norm partials reduce via shfl within the half-warp.
// ---------------------------------------------------------------------------
__global__ __launch_bounds__(512) void write_head_kernel(
    const float* __restrict__ w_prev,
    const float* __restrict__ memory,
    float* __restrict__ out_w,
    float* __restrict__ out_mem)
{
    __shared__ float sK[64], sE[64], sA[64];
    __shared__ float sDot[256], sNsq[256];
    __shared__ float sWg[256];
    __shared__ float sW[256];
    __shared__ float sRed[16];
    __shared__ float sKred[2];
    __shared__ float sScal[8];             // beta,g,s0..s2,gamma

    const int b = blockIdx.x;
    const int tid = threadIdx.x;
    const int widx = tid >> 5;
    const float* Grow = g_G + (size_t)b * G_COLS;

    // gate loads + tiny activations
    if (tid < 64) {
        float kv = Grow[tid];
        sK[tid] = kv;
        sE[tid] = sigmoid_f(Grow[70 + tid]);
        sA[tid] = Grow[134 + tid];
        float kk = kv * kv;
#pragma unroll
        for (int o = 16; o > 0; o >>= 1) kk += __shfl_xor_sync(0xffffffffu, kk, o);
        if ((tid & 31) == 0) sKred[tid >> 5] = kk;
    } else if (tid == 64) {
        sScal[0] = softplus_f(Grow[64]);            // beta
    } else if (tid == 65) {
        sScal[1] = sigmoid_f(Grow[65]);             // g
    } else if (tid == 66) {
        sScal[5] = 1.f + softplus_f(Grow[69]);      // gamma
    } else if (tid == 67) {
        float x0 = Grow[66], x1 = Grow[67], x2 = Grow[68];
        float mx = fmaxf(x0, fmaxf(x1, x2));
        float e0 = expf(x0 - mx), e1 = expf(x1 - mx), e2 = expf(x2 - mx);
        float inv = 1.f / (e0 + e1 + e2);
        sScal[2] = e0 * inv; sScal[3] = e1 * inv; sScal[4] = e2 * inv;
    }

    // load memory tile into registers (coalesced, streaming; all 8 in flight)
    const float4* memv = (const float4*)(memory + (size_t)b * (N_DIM * M_DIM));
    float4 v[8];
#pragma unroll
    for (int ii = 0; ii < 8; ++ii)
        v[ii] = __ldcs(memv + ii * 512 + tid);

    __syncthreads();                       // sK visible

    // per-row dot(k) + norm^2 partials; reduce inside owning half-warp
    {
        const int m0 = (tid & 15) * 4;
        const float k0 = sK[m0], k1 = sK[m0 + 1], k2 = sK[m0 + 2], k3 = sK[m0 + 3];
#pragma unroll
        for (int ii = 0; ii < 8; ++ii) {
            float d = v[ii].x * k0 + v[ii].y * k1 + v[ii].z * k2 + v[ii].w * k3;
            float q = v[ii].x * v[ii].x + v[ii].y * v[ii].y
                    + v[ii].z * v[ii].z + v[ii].w * v[ii].w;
#pragma unroll
            for (int o = 8; o > 0; o >>= 1) {
                d += __shfl_xor_sync(0xffffffffu, d, o);
                q += __shfl_xor_sync(0xffffffffu, q, o);
            }
            if ((tid & 15) == 0) {
                const int n = ii * 32 + (tid >> 4);
                sDot[n] = d;
                sNsq[n] = q;
            }
        }
    }
    __syncthreads();

    const float knorm = sqrtf(sKred[0] + sKred[1]);
    const float beta  = sScal[0];
    const float g     = sScal[1];
    const float s0    = sScal[2], s1 = sScal[3], s2 = sScal[4];
    const float gamma = sScal[5];

    // content addressing: thread per slot n (tid < 256)
    const int n = tid;
    float logit = -INFINITY;
    if (tid < 256) {
        float cosv = sDot[n] / (fmaxf(sqrtf(sNsq[n]), 1e-8f) * fmaxf(knorm, 1e-8f));
        logit = beta * cosv;
    }

    // block max over 512 threads
    float mv = logit;
#pragma unroll
    for (int o = 16; o > 0; o >>= 1) mv = fmaxf(mv, __shfl_xor_sync(0xffffffffu, mv, o));
    if ((tid & 31) == 0) sRed[widx] = mv;
    __syncthreads();
    float mx = sRed[0];
#pragma unroll
    for (int i = 1; i < 16; i++) mx = fmaxf(mx, sRed[i]);

    float ex = (tid < 256) ? expf(logit - mx) : 0.f;
    float sv = ex;
#pragma unroll
    for (int o = 16; o > 0; o >>= 1) sv += __shfl_xor_sync(0xffffffffu, sv, o);
    __syncthreads();                       // sRed consumed above
    if ((tid & 31) == 0) sRed[widx] = sv;
    __syncthreads();
    float sum = 0.f;
#pragma unroll
    for (int i = 0; i < 16; i++) sum += sRed[i];

    float wg = 0.f;
    if (tid < 256) {
        float wc = ex / sum;
        wg = g * wc + (1.f - g) * w_prev[(size_t)b * N_DIM + n];
        sWg[n] = wg;
    }
    __syncthreads();

    float wpow = 0.f;
    if (tid < 256) {
        float wsh = s0 * sWg[(n + 255) & 255] + s1 * wg + s2 * sWg[(n + 1) & 255];
        wpow = powf(wsh, gamma);
    }
    float pv = wpow;
#pragma unroll
    for (int o = 16; o > 0; o >>= 1) pv += __shfl_xor_sync(0xffffffffu, pv, o);
    __syncthreads();
    if ((tid & 31) == 0) sRed[widx] = pv;
    __syncthreads();
    float psum = 0.f;
#pragma unroll
    for (int i = 0; i < 16; i++) psum += sRed[i];

    if (tid < 256) {
        float wfin = wpow / (psum + 1e-16f);
        out_w[(size_t)b * N_DIM + n] = wfin;
        sW[n] = wfin;
    }
    __syncthreads();

    // erase/add update straight from registers, streamed out
    {
        const int m0 = (tid & 15) * 4;
        const float4 e4 = *reinterpret_cast<const float4*>(sE + m0);
        const float4 a4 = *reinterpret_cast<const float4*>(sA + m0);
        float4* outv = (float4*)(out_mem + (size_t)b * (N_DIM * M_DIM));
#pragma unroll
        for (int ii = 0; ii < 8; ++ii) {
            const float wn = sW[ii * 32 + (tid >> 4)];
            float4 r;
            r.x = v[ii].x * (1.f - wn * e4.x) + wn * a4.x;
            r.y = v[ii].y * (1.f - wn * e4.y) + wn * a4.y;
            r.z = v[ii].z * (1.f - wn * e4.z) + wn * a4.z;
            r.w = v[ii].w * (1.f - wn * e4.w) + wn * a4.w;
            __stcs(outv + ii * 512 + tid, r);
        }
    }
}

// ---------------------------------------------------------------------------
extern "C" void kernel_launch(void* const* d_in, const int* in_sizes, int n_in,
                              void* d_out, int out_size)
{
    const float* emb    = (const float*)d_in[0];
    const float* w_prev = (const float*)d_in[1];
    const float* memory = (const float*)d_in[2];
    const float* Wk  = (const float*)d_in[3];  const float* bk  = (const float*)d_in[4];
    const float* Wb  = (const float*)d_in[5];  const float* bb  = (const float*)d_in[6];
    const float* Wg  = (const float*)d_in[7];  const float* bg  = (const float*)d_in[8];
    const float* Ws  = (const float*)d_in[9];  const float* bs  = (const float*)d_in[10];
    const float* Wgm = (const float*)d_in[11]; const float* bgm = (const float*)d_in[12];
    const float* We  = (const float*)d_in[13]; const float* be  = (const float*)d_in[14];
    const float* Wa  = (const float*)d_in[15]; const float* ba  = (const float*)d_in[16];

    float* out_w   = (float*)d_out;                       // [B, N]
    float* out_mem = out_w + (size_t)B_SZ * N_DIM;        // [B, N, M]

    cudaFuncSetAttribute(gates_gemm_mma,
                         cudaFuncAttributeMaxDynamicSharedMemorySize, GEMM_SMEM);

    conv_w_kernel<<<256, 256>>>(Wk, bk, Wb, bb, Wg, bg, Ws, bs,
                                Wgm, bgm, We, be, Wa, ba);
    gates_gemm_mma<<<dim3(B_SZ / 64, 2), 256, GEMM_SMEM>>>(emb);
    write_head_kernel<<<B_SZ, 512>>>(w_prev, memory, out_w, out_mem);
}